// round 2
// baseline (speedup 1.0000x reference)
#include <cuda_runtime.h>
#include <math_constants.h>

// ---------------------------------------------------------------------------
// RVQBottleneck: 2-stage residual VQ.
//   out[r] = emb0[argmin_j ||x_r - e0_j||^2] + emb1[argmin_j ||res_r - e1_j||^2]
// (gray-code round trip in the reference is the identity; STE passthrough is
//  replicated as fl(x + fl(decoded - x)) ).
// Distances replicate the reference expression tree exactly:
//   dist = fl( fl(x2 + e2) - 2*xe ),  argmin with first-index tie break.
// ---------------------------------------------------------------------------

#define D        512
#define MAXROWS  32768
#define NCMAX    1024

#define BM 128
#define BN 128
#define BK 32
#define SMPAD 4
#define SMLD (BM + SMPAD)

// Scratch (allocation-free: __device__ globals)
__device__ float g_resid[(size_t)MAXROWS * D];
__device__ float g_x2[MAXROWS];
__device__ float g_r2[MAXROWS];
__device__ float g_e2a[NCMAX];
__device__ float g_e2b[NCMAX];
__device__ int   g_idx0[MAXROWS];
__device__ int   g_idx1[MAXROWS];

// ---------------------------------------------------------------------------
// Row squared-norm: one warp per row (D=512 -> 4 float4 per lane).
// ---------------------------------------------------------------------------
__global__ void rownorm_kernel(const float* __restrict__ src,
                               float* __restrict__ dst, int nrows)
{
    int row  = blockIdx.x * 8 + (threadIdx.x >> 5);
    if (row >= nrows) return;
    int lane = threadIdx.x & 31;
    const float4* p = (const float4*)(src + (size_t)row * D);
    float s = 0.f;
#pragma unroll
    for (int i = 0; i < D / 128; i++) {
        float4 v = p[lane + 32 * i];
        s += v.x * v.x + v.y * v.y + v.z * v.z + v.w * v.w;
    }
#pragma unroll
    for (int o = 16; o; o >>= 1) s += __shfl_down_sync(0xFFFFFFFFu, s, o);
    if (lane == 0) dst[row] = s;
}

// ---------------------------------------------------------------------------
// Fused GEMM + argmin stage.
// Block: 256 threads = 16x16; tile BM(128 rows) x BN(128 cols), loops over all
// ncodes columns so the argmin is block-local. 8x8 microtile per thread.
// ---------------------------------------------------------------------------
__global__ __launch_bounds__(256, 2)
void stage_kernel(const float* __restrict__ X, const float* __restrict__ E,
                  const float* __restrict__ rn2, const float* __restrict__ en2,
                  int* __restrict__ outIdx, int ncodes)
{
    __shared__ float As[BK][SMLD];
    __shared__ float Bs[BK][SMLD];

    const int tid = threadIdx.x;
    const int tx  = tid & 15;      // column group
    const int ty  = tid >> 4;      // row group
    const int rowBase = blockIdx.x * BM;

    float myx2[8];
#pragma unroll
    for (int i = 0; i < 8; i++) myx2[i] = __ldg(&rn2[rowBase + ty * 8 + i]);

    float bestd[8];
    int   besti[8];
#pragma unroll
    for (int i = 0; i < 8; i++) { bestd[i] = CUDART_INF_F; besti[i] = 0; }

    for (int colBase = 0; colBase < ncodes; colBase += BN) {
        float acc[8][8];
#pragma unroll
        for (int i = 0; i < 8; i++)
#pragma unroll
            for (int j = 0; j < 8; j++) acc[i][j] = 0.f;

        for (int kBase = 0; kBase < D; kBase += BK) {
            // Cooperative load: 128x32 tiles of X and E, transposed into smem.
#pragma unroll
            for (int l = 0; l < 4; l++) {
                int f  = tid + 256 * l;      // float4 index 0..1023
                int r  = f >> 3;             // tile row 0..127
                int kc = (f & 7) << 2;       // k offset 0..28
                float4 v = *(const float4*)(X + (size_t)(rowBase + r) * D + kBase + kc);
                As[kc + 0][r] = v.x; As[kc + 1][r] = v.y;
                As[kc + 2][r] = v.z; As[kc + 3][r] = v.w;
                float4 w = *(const float4*)(E + (size_t)(colBase + r) * D + kBase + kc);
                Bs[kc + 0][r] = w.x; Bs[kc + 1][r] = w.y;
                Bs[kc + 2][r] = w.z; Bs[kc + 3][r] = w.w;
            }
            __syncthreads();

#pragma unroll 8
            for (int k = 0; k < BK; k++) {
                float a[8], b[8];
                *(float4*)&a[0] = *(const float4*)&As[k][ty * 8];
                *(float4*)&a[4] = *(const float4*)&As[k][ty * 8 + 4];
                *(float4*)&b[0] = *(const float4*)&Bs[k][tx * 8];
                *(float4*)&b[4] = *(const float4*)&Bs[k][tx * 8 + 4];
#pragma unroll
                for (int i = 0; i < 8; i++)
#pragma unroll
                    for (int j = 0; j < 8; j++)
                        acc[i][j] = __fmaf_rn(a[i], b[j], acc[i][j]);
            }
            __syncthreads();
        }

        // Epilogue: dist = fl(fl(x2+e2) - 2*xe), track (min, first index).
#pragma unroll
        for (int j = 0; j < 8; j++) {
            int col = colBase + tx * 8 + j;
            float e2v = __ldg(&en2[col]);
#pragma unroll
            for (int i = 0; i < 8; i++) {
                float t  = __fadd_rn(myx2[i], e2v);
                float dd = __fmaf_rn(-2.0f, acc[i][j], t);
                if (dd < bestd[i] || (dd == bestd[i] && col < besti[i])) {
                    bestd[i] = dd; besti[i] = col;
                }
            }
        }
    }

    // Reduce the 16 column-group lanes (same ty, consecutive lanes) per row.
#pragma unroll
    for (int i = 0; i < 8; i++) {
        float d  = bestd[i];
        int   ix = besti[i];
#pragma unroll
        for (int o = 8; o; o >>= 1) {
            float od = __shfl_down_sync(0xFFFFFFFFu, d,  o, 16);
            int   oi = __shfl_down_sync(0xFFFFFFFFu, ix, o, 16);
            if (od < d || (od == d && oi < ix)) { d = od; ix = oi; }
        }
        if (tx == 0) outIdx[rowBase + ty * 8 + i] = ix;
    }
}

// ---------------------------------------------------------------------------
// Residual: R[r] = X[r] - E[idx[r]] (exact fp32, same as ref) + fused ||R||^2.
// One block of 128 threads per row (one float4 per thread).
// ---------------------------------------------------------------------------
__global__ void resid_kernel(const float* __restrict__ X, const float* __restrict__ E,
                             const int* __restrict__ idx, float* __restrict__ R,
                             float* __restrict__ r2)
{
    int row = blockIdx.x;
    int t   = threadIdx.x;     // 0..127
    int c   = idx[row];
    float4 xv = ((const float4*)(X + (size_t)row * D))[t];
    float4 ev = ((const float4*)(E + (size_t)c   * D))[t];
    float4 rv = make_float4(xv.x - ev.x, xv.y - ev.y, xv.z - ev.z, xv.w - ev.w);
    ((float4*)(R + (size_t)row * D))[t] = rv;

    float s = rv.x * rv.x + rv.y * rv.y + rv.z * rv.z + rv.w * rv.w;
#pragma unroll
    for (int o = 16; o; o >>= 1) s += __shfl_down_sync(0xFFFFFFFFu, s, o);
    __shared__ float red[4];
    if ((t & 31) == 0) red[t >> 5] = s;
    __syncthreads();
    if (t == 0) r2[row] = red[0] + red[1] + red[2] + red[3];
}

// ---------------------------------------------------------------------------
// Output: out = fl(x + fl(fl(e0+e1) - x))  (replicates reference STE rounding)
// ---------------------------------------------------------------------------
__global__ void out_kernel(const float* __restrict__ X, const float* __restrict__ E0,
                           const float* __restrict__ E1, const int* __restrict__ i0,
                           const int* __restrict__ i1, float* __restrict__ out)
{
    int row = blockIdx.x;
    int t   = threadIdx.x;     // 0..127
    int c0  = i0[row];
    int c1  = i1[row];
    float4 xv = ((const float4*)(X  + (size_t)row * D))[t];
    float4 a  = ((const float4*)(E0 + (size_t)c0  * D))[t];
    float4 b  = ((const float4*)(E1 + (size_t)c1  * D))[t];
    float4 o;
    o.x = __fadd_rn(xv.x, __fadd_rn(__fadd_rn(a.x, b.x), -xv.x));
    o.y = __fadd_rn(xv.y, __fadd_rn(__fadd_rn(a.y, b.y), -xv.y));
    o.z = __fadd_rn(xv.z, __fadd_rn(__fadd_rn(a.z, b.z), -xv.z));
    o.w = __fadd_rn(xv.w, __fadd_rn(__fadd_rn(a.w, b.w), -xv.w));
    ((float4*)(out + (size_t)row * D))[t] = o;
}

// ---------------------------------------------------------------------------
extern "C" void kernel_launch(void* const* d_in, const int* in_sizes, int n_in,
                              void* d_out, int out_size)
{
    const float* x  = (const float*)d_in[0];
    const float* e0 = (const float*)d_in[1];
    const float* e1 = (const float*)d_in[2];
    float* out = (float*)d_out;

    int rows = in_sizes[0] / D;   // 32768
    int nc   = in_sizes[1] / D;   // 1024

    float *px2, *pr2, *pe2a, *pe2b, *pres;
    int   *pi0, *pi1;
    cudaGetSymbolAddress((void**)&px2,  g_x2);
    cudaGetSymbolAddress((void**)&pr2,  g_r2);
    cudaGetSymbolAddress((void**)&pe2a, g_e2a);
    cudaGetSymbolAddress((void**)&pe2b, g_e2b);
    cudaGetSymbolAddress((void**)&pres, g_resid);
    cudaGetSymbolAddress((void**)&pi0,  g_idx0);
    cudaGetSymbolAddress((void**)&pi1,  g_idx1);

    rownorm_kernel<<<(rows + 7) / 8, 256>>>(x,  px2,  rows);
    rownorm_kernel<<<(nc   + 7) / 8, 256>>>(e0, pe2a, nc);
    rownorm_kernel<<<(nc   + 7) / 8, 256>>>(e1, pe2b, nc);

    stage_kernel<<<rows / BM, 256>>>(x, e0, px2, pe2a, pi0, nc);
    resid_kernel<<<rows, 128>>>(x, e0, pi0, pres, pr2);
    stage_kernel<<<rows / BM, 256>>>(pres, e1, pr2, pe2b, pi1, nc);
    out_kernel<<<rows, 128>>>(x, e0, e1, pi0, pi1, out);
}